// round 8
// baseline (speedup 1.0000x reference)
#include <cuda_runtime.h>
#include <cuda_bf16.h>
#include <stdint.h>
#include <math.h>

// ---------------------------------------------------------------------------
// Problem constants
// ---------------------------------------------------------------------------
#define TOK      16384
#define DMODEL   2048
#define E3       6144
#define NHEAD    16
#define HD       128
#define SEQ      64
#define NBATCH   256

// Scratch (device globals: allocation rules forbid cudaMalloc)
__device__ float g_qkv[(size_t)TOK * E3];
__device__ float g_att[(size_t)TOK * DMODEL];
__device__ float g_xr [(size_t)TOK * DMODEL];
__device__ float g_wqr[(size_t)E3  * DMODEL];
__device__ float g_wor[(size_t)DMODEL * DMODEL];

// ---------------------------------------------------------------------------
// TF32 helpers
// ---------------------------------------------------------------------------
__device__ __forceinline__ float round_tf32(float x) {
    uint32_t u;
    asm("cvt.rna.tf32.f32 %0, %1;" : "=r"(u) : "f"(x));
    return __uint_as_float(u);
}

__global__ void __launch_bounds__(256)
round_tf32_kernel(const float4* __restrict__ in, float4* __restrict__ out, int n4)
{
    int i = blockIdx.x * blockDim.x + threadIdx.x;
    if (i < n4) {
        float4 v = in[i];
        v.x = round_tf32(v.x);
        v.y = round_tf32(v.y);
        v.z = round_tf32(v.z);
        v.w = round_tf32(v.w);
        out[i] = v;
    }
}

// ---------------------------------------------------------------------------
// TF32 tensor-core NT GEMM: C[M,N] = A[M,K] @ B[N,K]^T + bias[N]
// CTA tile 128x256, BK=32, 3-stage cp.async, one barrier per k-iter.
// 256 threads = 8 warps (2m x 4n), warp tile 64x64 -> per k8-step:
//   8 ldmatrix.x4 feed 32 m16n8k8 MMAs (4:1 MMA:LDSM, smem port ~50%).
// Smem rows [LDK=36] (16B pad) -> conflict-free ldmatrix.
// Inputs tf32-pre-rounded (rna); fp32 accumulation.
// ---------------------------------------------------------------------------
#define BM 128
#define BN 256
#define BK 32
#define STAGES 3
#define LDK 36
#define A_STG_FLOATS (BM * LDK)                       // 4608
#define B_STG_FLOATS (BN * LDK)                       // 9216
#define A_STG_BYTES  (A_STG_FLOATS * 4)               // 18432
#define B_STG_BYTES  (B_STG_FLOATS * 4)               // 36864
#define GEMM_SMEM    (STAGES * (A_STG_BYTES + B_STG_BYTES))  // 165888

__device__ __forceinline__ void cp16(uint32_t dst, const float* src) {
    asm volatile("cp.async.cg.shared.global [%0], [%1], 16;\n" :: "r"(dst), "l"(src));
}
__device__ __forceinline__ void cp_commit() {
    asm volatile("cp.async.commit_group;\n");
}
__device__ __forceinline__ void ldsm4(uint32_t (&r)[4], uint32_t addr) {
    asm volatile("ldmatrix.sync.aligned.m8n8.x4.shared.b16 {%0,%1,%2,%3}, [%4];\n"
                 : "=r"(r[0]), "=r"(r[1]), "=r"(r[2]), "=r"(r[3]) : "r"(addr));
}
__device__ __forceinline__ void mma_tf32(float (&c)[4], const uint32_t (&a)[4],
                                         uint32_t b0, uint32_t b1) {
    asm volatile(
        "mma.sync.aligned.m16n8k8.row.col.f32.tf32.tf32.f32 "
        "{%0,%1,%2,%3},{%4,%5,%6,%7},{%8,%9},{%0,%1,%2,%3};\n"
        : "+f"(c[0]), "+f"(c[1]), "+f"(c[2]), "+f"(c[3])
        : "r"(a[0]), "r"(a[1]), "r"(a[2]), "r"(a[3]), "r"(b0), "r"(b1));
}

__global__ void __launch_bounds__(256, 1)
gemm_nt_tc(const float* __restrict__ A, const float* __restrict__ Bm,
           const float* __restrict__ bias, float* __restrict__ C,
           int M, int N, int K)
{
    extern __shared__ float sm[];
    float* As = sm;                               // [STAGES][A_STG_FLOATS]
    float* Bs = sm + STAGES * A_STG_FLOATS;       // [STAGES][B_STG_FLOATS]

    const int tid  = threadIdx.x;
    const int bm   = blockIdx.y * BM;
    const int bn   = blockIdx.x * BN;
    const int warp = tid >> 5;
    const int lane = tid & 31;
    const int wm   = warp >> 2;   // 0..1
    const int wn   = warp & 3;    // 0..3

    const uint32_t smA = (uint32_t)__cvta_generic_to_shared(As);
    const uint32_t smB = (uint32_t)__cvta_generic_to_shared(Bs);

    // gmem->smem mapping: per stage A = 1024 float4, B = 2048 float4.
    // per thread: 4 A + 8 B cp.asyncs.
    const float* AgP[4]; uint32_t sAP[4];
#pragma unroll
    for (int i = 0; i < 4; i++) {
        const int c   = tid + i * 256;   // 0..1023
        const int row = c >> 3;          // 0..127
        const int f4  = c & 7;
        AgP[i] = A + (size_t)(bm + row) * K + f4 * 4;
        sAP[i] = smA + (uint32_t)((row * LDK + f4 * 4) * 4);
    }
    const float* BgP[8]; uint32_t sBP[8];
#pragma unroll
    for (int i = 0; i < 8; i++) {
        const int c   = tid + i * 256;   // 0..2047
        const int row = c >> 3;          // 0..255
        const int f4  = c & 7;
        BgP[i] = Bm + (size_t)(bn + row) * K + f4 * 4;
        sBP[i] = smB + (uint32_t)((row * LDK + f4 * 4) * 4);
    }

    // ldmatrix per-lane fragment bases
    const int lrow = lane & 15;
    const int lk   = (lane >> 4) << 2;
    const uint32_t aFrag = smA + (uint32_t)(((wm * 64 + lrow) * LDK + lk) * 4);
    const uint32_t bFrag = smB + (uint32_t)(((wn * 64 + lrow) * LDK + lk) * 4);

    float c[4][8][4];
#pragma unroll
    for (int i = 0; i < 4; i++)
#pragma unroll
        for (int j = 0; j < 8; j++)
#pragma unroll
            for (int r = 0; r < 4; r++) c[i][j][r] = 0.0f;

    const int NT = K / BK;

    // prologue: stages 0..STAGES-2
#pragma unroll
    for (int p = 0; p < STAGES - 1; p++) {
        const int koff = p * BK;
        const uint32_t ao = (uint32_t)(p * A_STG_BYTES);
        const uint32_t bo = (uint32_t)(p * B_STG_BYTES);
#pragma unroll
        for (int i = 0; i < 4; i++) cp16(sAP[i] + ao, AgP[i] + koff);
#pragma unroll
        for (int i = 0; i < 8; i++) cp16(sBP[i] + bo, BgP[i] + koff);
        cp_commit();
    }

    int st = 0;
    for (int s = 0; s < NT; s++) {
        if (s + 1 < NT) {
            asm volatile("cp.async.wait_group 1;\n");
        } else {
            asm volatile("cp.async.wait_group 0;\n");
        }
        __syncthreads();

        // prefetch stage s+STAGES-1 into the slot freed by stage s-1
        if (s + STAGES - 1 < NT) {
            const int koff = (s + STAGES - 1) * BK;
            const int slot = (s + STAGES - 1) % STAGES;
            const uint32_t ao = (uint32_t)(slot * A_STG_BYTES);
            const uint32_t bo = (uint32_t)(slot * B_STG_BYTES);
#pragma unroll
            for (int i = 0; i < 4; i++) cp16(sAP[i] + ao, AgP[i] + koff);
#pragma unroll
            for (int i = 0; i < 8; i++) cp16(sBP[i] + bo, BgP[i] + koff);
            cp_commit();
        }

        // compute stage st: 4 k8-steps, 32 MMAs each
        {
            const uint32_t aOff = aFrag + (uint32_t)(st * A_STG_BYTES);
            const uint32_t bOff = bFrag + (uint32_t)(st * B_STG_BYTES);
#pragma unroll
            for (int ks = 0; ks < 4; ks++) {
                uint32_t a[4][4];
#pragma unroll
                for (int am = 0; am < 4; am++)
                    ldsm4(a[am], aOff + ks * 32 + am * (16 * LDK * 4));
                uint32_t b[4][4];
#pragma unroll
                for (int pr = 0; pr < 4; pr++)
                    ldsm4(b[pr], bOff + ks * 32 + pr * (16 * LDK * 4));
#pragma unroll
                for (int am = 0; am < 4; am++)
#pragma unroll
                    for (int an = 0; an < 8; an++)
                        mma_tf32(c[am][an], a[am],
                                 b[an >> 1][an & 1], b[an >> 1][2 + (an & 1)]);
            }
        }
        st = (st + 1 == STAGES) ? 0 : st + 1;
    }

    // epilogue
    const int erow = lane >> 2;
    const int ecol = (lane & 3) * 2;
#pragma unroll
    for (int am = 0; am < 4; am++) {
        const int row = bm + wm * 64 + am * 16 + erow;
#pragma unroll
        for (int an = 0; an < 8; an++) {
            const int col = bn + wn * 64 + an * 8 + ecol;
            const float b0v = __ldg(bias + col);
            const float b1v = __ldg(bias + col + 1);
            float* p0 = C + (size_t)row * N + col;
            float* p1 = C + (size_t)(row + 8) * N + col;
            p0[0] = c[am][an][0] + b0v;
            p0[1] = c[am][an][1] + b1v;
            p1[0] = c[am][an][2] + b0v;
            p1[1] = c[am][an][3] + b1v;
        }
    }
}

// ---------------------------------------------------------------------------
// Attention per (batch, head): K/V/P in smem (83KB -> 2 CTA/SM), Q streamed
// from gmem (L1-resident, 8x reuse). fp32; output tf32-rounded for GEMM3.
// ---------------------------------------------------------------------------
#define K_PAD 129
#define V_PAD 132
#define P_PAD 65
#define ATTN_SMEM_FLOATS (SEQ * K_PAD + SEQ * V_PAD + SEQ * P_PAD)
#define ATTN_SMEM_BYTES  (ATTN_SMEM_FLOATS * 4)

__global__ void __launch_bounds__(128)
attn64(const float* __restrict__ qkv, float* __restrict__ att)
{
    extern __shared__ float smn[];
    float* Ks = smn;
    float* Vs = Ks + SEQ * K_PAD;
    float* Ps = Vs + SEQ * V_PAD;

    const int bh  = blockIdx.x;
    const int b   = bh >> 4;
    const int h   = bh & 15;
    const int tid = threadIdx.x;

    const float* base = qkv + (size_t)b * SEQ * E3 + h * HD;

    // load K, V tiles (2 threads per row, 64 floats each)
    {
        const int r  = tid >> 1;
        const int cp = (tid & 1) * 64;
        const float* src = base + (size_t)r * E3 + cp;
        float* dk = Ks + r * K_PAD + cp;
        float* dv = Vs + r * V_PAD + cp;
#pragma unroll
        for (int i = 0; i < 64; i += 4) {
            float4 k4 = *(const float4*)(src + DMODEL + i);
            float4 v4 = *(const float4*)(src + 2 * DMODEL + i);
            dk[i] = k4.x; dk[i+1] = k4.y; dk[i+2] = k4.z; dk[i+3] = k4.w;
            *(float4*)(dv + i) = v4;
        }
    }
    __syncthreads();

    // scores: thread computes 4q x 8k, Q from gmem (L1)
    {
        const int tq = (tid >> 3) * 4;
        const int tk = (tid & 7) * 8;
        const float* q0 = base + (size_t)(tq + 0) * E3;
        const float* q1 = base + (size_t)(tq + 1) * E3;
        const float* q2 = base + (size_t)(tq + 2) * E3;
        const float* q3 = base + (size_t)(tq + 3) * E3;
        float acc[4][8];
#pragma unroll
        for (int i = 0; i < 4; i++)
#pragma unroll
            for (int j = 0; j < 8; j++) acc[i][j] = 0.0f;

        for (int kd = 0; kd < HD; kd += 4) {
            float qv[4][4];
            *(float4*)qv[0] = __ldg((const float4*)(q0 + kd));
            *(float4*)qv[1] = __ldg((const float4*)(q1 + kd));
            *(float4*)qv[2] = __ldg((const float4*)(q2 + kd));
            *(float4*)qv[3] = __ldg((const float4*)(q3 + kd));
#pragma unroll
            for (int kk = 0; kk < 4; kk++) {
                float kv[8];
#pragma unroll
                for (int j = 0; j < 8; j++) kv[j] = Ks[(tk + j) * K_PAD + kd + kk];
#pragma unroll
                for (int i = 0; i < 4; i++)
#pragma unroll
                    for (int j = 0; j < 8; j++)
                        acc[i][j] = fmaf(qv[i][kk], kv[j], acc[i][j]);
            }
        }

        const float scale = 0.022097086912079608f;  // 1/sqrt(2048)
#pragma unroll
        for (int i = 0; i < 4; i++) {
            const int q = tq + i;
#pragma unroll
            for (int j = 0; j < 8; j++) {
                const int k = tk + j;
                Ps[q * P_PAD + k] = (k <= q) ? acc[i][j] * scale : -1e30f;
            }
        }
    }
    __syncthreads();

    // column softmax over q (axis=-2), valid q in [k, 63]
    if (tid < SEQ) {
        const int k = tid;
        float m = -1e30f;
        for (int q = k; q < SEQ; q++) m = fmaxf(m, Ps[q * P_PAD + k]);
        float ssum = 0.0f;
        for (int q = k; q < SEQ; q++) {
            float e = __expf(Ps[q * P_PAD + k] - m);
            Ps[q * P_PAD + k] = e;
            ssum += e;
        }
        const float inv = 1.0f / ssum;
        for (int q = 0; q < SEQ; q++)
            Ps[q * P_PAD + k] = (q < k) ? 0.0f : Ps[q * P_PAD + k] * inv;
    }
    __syncthreads();

    // PV: thread computes 8q x 8c
    {
        const int tq = (tid >> 4) * 8;
        const int tc = (tid & 15) * 8;
        float acc[8][8];
#pragma unroll
        for (int i = 0; i < 8; i++)
#pragma unroll
            for (int j = 0; j < 8; j++) acc[i][j] = 0.0f;

        for (int k = 0; k < SEQ; k++) {
            float pv[8], vv[8];
#pragma unroll
            for (int i = 0; i < 8; i++) pv[i] = Ps[(tq + i) * P_PAD + k];
            *(float4*)(vv)     = *(const float4*)&Vs[k * V_PAD + tc];
            *(float4*)(vv + 4) = *(const float4*)&Vs[k * V_PAD + tc + 4];
#pragma unroll
            for (int i = 0; i < 8; i++)
#pragma unroll
                for (int j = 0; j < 8; j++)
                    acc[i][j] = fmaf(pv[i], vv[j], acc[i][j]);
        }

        float* outp = att + (size_t)b * SEQ * DMODEL + h * HD;
#pragma unroll
        for (int i = 0; i < 8; i++)
#pragma unroll
            for (int j = 0; j < 8; j++)
                outp[(size_t)(tq + i) * DMODEL + tc + j] = round_tf32(acc[i][j]);
    }
}

// ---------------------------------------------------------------------------
// Launch
// ---------------------------------------------------------------------------
extern "C" void kernel_launch(void* const* d_in, const int* in_sizes, int n_in,
                              void* d_out, int out_size)
{
    const float* x     = (const float*)d_in[0];
    const float* W_qkv = (const float*)d_in[1];
    const float* b_qkv = (const float*)d_in[2];
    const float* W_out = (const float*)d_in[3];
    const float* b_out = (const float*)d_in[4];
    float* out = (float*)d_out;

    float *qkv = nullptr, *att = nullptr, *xr = nullptr, *wqr = nullptr, *wor = nullptr;
    cudaGetSymbolAddress((void**)&qkv, g_qkv);
    cudaGetSymbolAddress((void**)&att, g_att);
    cudaGetSymbolAddress((void**)&xr,  g_xr);
    cudaGetSymbolAddress((void**)&wqr, g_wqr);
    cudaGetSymbolAddress((void**)&wor, g_wor);

    cudaFuncSetAttribute(gemm_nt_tc, cudaFuncAttributeMaxDynamicSharedMemorySize, GEMM_SMEM);
    cudaFuncSetAttribute(attn64, cudaFuncAttributeMaxDynamicSharedMemorySize, ATTN_SMEM_BYTES);

    // 0) unbiased tf32 rounding of GEMM inputs
    {
        int n4x = TOK * DMODEL / 4;
        round_tf32_kernel<<<n4x / 256, 256>>>((const float4*)x, (float4*)xr, n4x);
        int n4q = E3 * DMODEL / 4;
        round_tf32_kernel<<<n4q / 256, 256>>>((const float4*)W_qkv, (float4*)wqr, n4q);
        int n4o = DMODEL * DMODEL / 4;
        round_tf32_kernel<<<n4o / 256, 256>>>((const float4*)W_out, (float4*)wor, n4o);
    }

    // 1) qkv = x @ W_qkv^T + b_qkv   [16384, 6144]
    {
        dim3 grid(E3 / BN, TOK / BM);   // 24 x 128
        gemm_nt_tc<<<grid, 256, GEMM_SMEM>>>(xr, wqr, b_qkv, qkv, TOK, E3, DMODEL);
    }

    // 2) attention per (b, h)
    {
        attn64<<<NBATCH * NHEAD, 128, ATTN_SMEM_BYTES>>>(qkv, att);
    }

    // 3) out = att @ W_out^T + b_out  [16384, 2048]
    {
        dim3 grid(DMODEL / BN, TOK / BM);   // 8 x 128
        gemm_nt_tc<<<grid, 256, GEMM_SMEM>>>(att, wor, b_out, out, TOK, DMODEL, DMODEL);
    }
}

// round 9
// speedup vs baseline: 1.0416x; 1.0416x over previous
#include <cuda_runtime.h>
#include <cuda_bf16.h>
#include <stdint.h>
#include <math.h>

// ---------------------------------------------------------------------------
// Problem constants
// ---------------------------------------------------------------------------
#define TOK      16384
#define DMODEL   2048
#define E3       6144
#define NHEAD    16
#define HD       128
#define SEQ      64
#define NBATCH   256

// Scratch (device globals: allocation rules forbid cudaMalloc)
__device__ float g_qkv[(size_t)TOK * E3];
__device__ float g_att[(size_t)TOK * DMODEL];
__device__ float g_xr [(size_t)TOK * DMODEL];
__device__ float g_wqr[(size_t)E3  * DMODEL];
__device__ float g_wor[(size_t)DMODEL * DMODEL];

// ---------------------------------------------------------------------------
// TF32 helpers
// ---------------------------------------------------------------------------
__device__ __forceinline__ float round_tf32(float x) {
    uint32_t u;
    asm("cvt.rna.tf32.f32 %0, %1;" : "=r"(u) : "f"(x));
    return __uint_as_float(u);
}

__global__ void __launch_bounds__(256)
round_tf32_kernel(const float4* __restrict__ in, float4* __restrict__ out, int n4)
{
    int i = blockIdx.x * blockDim.x + threadIdx.x;
    if (i < n4) {
        float4 v = in[i];
        v.x = round_tf32(v.x);
        v.y = round_tf32(v.y);
        v.z = round_tf32(v.z);
        v.w = round_tf32(v.w);
        out[i] = v;
    }
}

// ---------------------------------------------------------------------------
// TF32 tensor-core NT GEMM: C[M,N] = A[M,K] @ B[N,K]^T + bias[N]
// CTA tile 128x128, BK=32, 3-stage cp.async, one barrier per k-iter.
// 128 threads = 4 warps (2m x 2n), warp tile 64x64:
//   per k8-step 8 ldmatrix.x4 feed 32 m16n8k8 MMAs (4:1).
// smem 110KB -> 2 CTAs/SM = 8 warps in 2 independent barrier domains.
// Crossbar traffic/SM/iter ~192KB (vs 256KB at 64x32 warp tiles).
// Smem rows [LDK=36] (16B pad) -> conflict-free ldmatrix.
// Inputs tf32-pre-rounded (rna); fp32 accumulation.
// ---------------------------------------------------------------------------
#define BM 128
#define BN 128
#define BK 32
#define STAGES 3
#define LDK 36
#define A_STG_FLOATS (BM * LDK)                       // 4608
#define STAGE_BYTES  (A_STG_FLOATS * 4)               // 18432
#define GEMM_SMEM    (STAGES * STAGE_BYTES * 2)       // 110592

__device__ __forceinline__ void cp16(uint32_t dst, const float* src) {
    asm volatile("cp.async.cg.shared.global [%0], [%1], 16;\n" :: "r"(dst), "l"(src));
}
__device__ __forceinline__ void cp_commit() {
    asm volatile("cp.async.commit_group;\n");
}
__device__ __forceinline__ void ldsm4(uint32_t (&r)[4], uint32_t addr) {
    asm volatile("ldmatrix.sync.aligned.m8n8.x4.shared.b16 {%0,%1,%2,%3}, [%4];\n"
                 : "=r"(r[0]), "=r"(r[1]), "=r"(r[2]), "=r"(r[3]) : "r"(addr));
}
__device__ __forceinline__ void mma_tf32(float (&c)[4], const uint32_t (&a)[4],
                                         uint32_t b0, uint32_t b1) {
    asm volatile(
        "mma.sync.aligned.m16n8k8.row.col.f32.tf32.tf32.f32 "
        "{%0,%1,%2,%3},{%4,%5,%6,%7},{%8,%9},{%0,%1,%2,%3};\n"
        : "+f"(c[0]), "+f"(c[1]), "+f"(c[2]), "+f"(c[3])
        : "r"(a[0]), "r"(a[1]), "r"(a[2]), "r"(a[3]), "r"(b0), "r"(b1));
}

__global__ void __launch_bounds__(128, 2)
gemm_nt_tc(const float* __restrict__ A, const float* __restrict__ Bm,
           const float* __restrict__ bias, float* __restrict__ C,
           int M, int N, int K)
{
    extern __shared__ float sm[];
    float* As = sm;                               // [STAGES][A_STG_FLOATS]
    float* Bs = sm + STAGES * A_STG_FLOATS;

    const int tid  = threadIdx.x;
    const int bm   = blockIdx.y * BM;
    const int bn   = blockIdx.x * BN;
    const int warp = tid >> 5;
    const int lane = tid & 31;
    const int wm   = warp >> 1;   // 0..1
    const int wn   = warp & 1;    // 0..1

    const uint32_t smA = (uint32_t)__cvta_generic_to_shared(As);
    const uint32_t smB = (uint32_t)__cvta_generic_to_shared(Bs);

    // gmem->smem mapping: per stage A = 1024 float4, B = 1024 float4;
    // 128 threads -> 8 A + 8 B cp.asyncs per thread.
    const float* AgP[8]; uint32_t sAP[8];
    const float* BgP[8]; uint32_t sBP[8];
#pragma unroll
    for (int i = 0; i < 8; i++) {
        const int c   = tid + i * 128;   // 0..1023
        const int row = c >> 3;          // 0..127
        const int f4  = c & 7;
        AgP[i] = A + (size_t)(bm + row) * K + f4 * 4;
        BgP[i] = Bm + (size_t)(bn + row) * K + f4 * 4;
        sAP[i] = smA + (uint32_t)((row * LDK + f4 * 4) * 4);
        sBP[i] = smB + (uint32_t)((row * LDK + f4 * 4) * 4);
    }

    // ldmatrix per-lane fragment bases
    const int lrow = lane & 15;
    const int lk   = (lane >> 4) << 2;
    const uint32_t aFrag = smA + (uint32_t)(((wm * 64 + lrow) * LDK + lk) * 4);
    const uint32_t bFrag = smB + (uint32_t)(((wn * 64 + lrow) * LDK + lk) * 4);

    float c[4][8][4];
#pragma unroll
    for (int i = 0; i < 4; i++)
#pragma unroll
        for (int j = 0; j < 8; j++)
#pragma unroll
            for (int r = 0; r < 4; r++) c[i][j][r] = 0.0f;

    const int NT = K / BK;

    // prologue: stages 0..STAGES-2
#pragma unroll
    for (int p = 0; p < STAGES - 1; p++) {
        const int koff = p * BK;
        const uint32_t so = (uint32_t)(p * STAGE_BYTES);
#pragma unroll
        for (int i = 0; i < 8; i++) {
            cp16(sAP[i] + so, AgP[i] + koff);
            cp16(sBP[i] + so, BgP[i] + koff);
        }
        cp_commit();
    }

    int st = 0;
    for (int s = 0; s < NT; s++) {
        if (s + 1 < NT) {
            asm volatile("cp.async.wait_group 1;\n");
        } else {
            asm volatile("cp.async.wait_group 0;\n");
        }
        __syncthreads();

        // prefetch stage s+STAGES-1 into the slot freed by stage s-1
        if (s + STAGES - 1 < NT) {
            const int koff = (s + STAGES - 1) * BK;
            const int slot = (s + STAGES - 1) % STAGES;
            const uint32_t so = (uint32_t)(slot * STAGE_BYTES);
#pragma unroll
            for (int i = 0; i < 8; i++) {
                cp16(sAP[i] + so, AgP[i] + koff);
                cp16(sBP[i] + so, BgP[i] + koff);
            }
            cp_commit();
        }

        // compute stage st: 4 k8-steps, 32 MMAs each
        {
            const uint32_t aOff = aFrag + (uint32_t)(st * STAGE_BYTES);
            const uint32_t bOff = bFrag + (uint32_t)(st * STAGE_BYTES);
#pragma unroll
            for (int ks = 0; ks < 4; ks++) {
                uint32_t a[4][4];
#pragma unroll
                for (int am = 0; am < 4; am++)
                    ldsm4(a[am], aOff + ks * 32 + am * (16 * LDK * 4));
                uint32_t b[4][4];
#pragma unroll
                for (int pr = 0; pr < 4; pr++)
                    ldsm4(b[pr], bOff + ks * 32 + pr * (16 * LDK * 4));
#pragma unroll
                for (int am = 0; am < 4; am++)
#pragma unroll
                    for (int an = 0; an < 8; an++)
                        mma_tf32(c[am][an], a[am],
                                 b[an >> 1][an & 1], b[an >> 1][2 + (an & 1)]);
            }
        }
        st = (st + 1 == STAGES) ? 0 : st + 1;
    }

    // epilogue
    const int erow = lane >> 2;
    const int ecol = (lane & 3) * 2;
#pragma unroll
    for (int am = 0; am < 4; am++) {
        const int row = bm + wm * 64 + am * 16 + erow;
#pragma unroll
        for (int an = 0; an < 8; an++) {
            const int col = bn + wn * 64 + an * 8 + ecol;
            const float b0v = __ldg(bias + col);
            const float b1v = __ldg(bias + col + 1);
            float* p0 = C + (size_t)row * N + col;
            float* p1 = C + (size_t)(row + 8) * N + col;
            p0[0] = c[am][an][0] + b0v;
            p0[1] = c[am][an][1] + b1v;
            p1[0] = c[am][an][2] + b0v;
            p1[1] = c[am][an][3] + b1v;
        }
    }
}

// ---------------------------------------------------------------------------
// Attention per (batch, head): K/V/P in smem (83KB -> 2 CTA/SM), Q streamed
// from gmem (L1-resident, 8x reuse). fp32; output tf32-rounded for GEMM3.
// ---------------------------------------------------------------------------
#define K_PAD 129
#define V_PAD 132
#define P_PAD 65
#define ATTN_SMEM_FLOATS (SEQ * K_PAD + SEQ * V_PAD + SEQ * P_PAD)
#define ATTN_SMEM_BYTES  (ATTN_SMEM_FLOATS * 4)

__global__ void __launch_bounds__(128)
attn64(const float* __restrict__ qkv, float* __restrict__ att)
{
    extern __shared__ float smn[];
    float* Ks = smn;
    float* Vs = Ks + SEQ * K_PAD;
    float* Ps = Vs + SEQ * V_PAD;

    const int bh  = blockIdx.x;
    const int b   = bh >> 4;
    const int h   = bh & 15;
    const int tid = threadIdx.x;

    const float* base = qkv + (size_t)b * SEQ * E3 + h * HD;

    // load K, V tiles (2 threads per row, 64 floats each)
    {
        const int r  = tid >> 1;
        const int cp = (tid & 1) * 64;
        const float* src = base + (size_t)r * E3 + cp;
        float* dk = Ks + r * K_PAD + cp;
        float* dv = Vs + r * V_PAD + cp;
#pragma unroll
        for (int i = 0; i < 64; i += 4) {
            float4 k4 = *(const float4*)(src + DMODEL + i);
            float4 v4 = *(const float4*)(src + 2 * DMODEL + i);
            dk[i] = k4.x; dk[i+1] = k4.y; dk[i+2] = k4.z; dk[i+3] = k4.w;
            *(float4*)(dv + i) = v4;
        }
    }
    __syncthreads();

    // scores: thread computes 4q x 8k, Q from gmem (L1)
    {
        const int tq = (tid >> 3) * 4;
        const int tk = (tid & 7) * 8;
        const float* q0 = base + (size_t)(tq + 0) * E3;
        const float* q1 = base + (size_t)(tq + 1) * E3;
        const float* q2 = base + (size_t)(tq + 2) * E3;
        const float* q3 = base + (size_t)(tq + 3) * E3;
        float acc[4][8];
#pragma unroll
        for (int i = 0; i < 4; i++)
#pragma unroll
            for (int j = 0; j < 8; j++) acc[i][j] = 0.0f;

        for (int kd = 0; kd < HD; kd += 4) {
            float qv[4][4];
            *(float4*)qv[0] = __ldg((const float4*)(q0 + kd));
            *(float4*)qv[1] = __ldg((const float4*)(q1 + kd));
            *(float4*)qv[2] = __ldg((const float4*)(q2 + kd));
            *(float4*)qv[3] = __ldg((const float4*)(q3 + kd));
#pragma unroll
            for (int kk = 0; kk < 4; kk++) {
                float kv[8];
#pragma unroll
                for (int j = 0; j < 8; j++) kv[j] = Ks[(tk + j) * K_PAD + kd + kk];
#pragma unroll
                for (int i = 0; i < 4; i++)
#pragma unroll
                    for (int j = 0; j < 8; j++)
                        acc[i][j] = fmaf(qv[i][kk], kv[j], acc[i][j]);
            }
        }

        const float scale = 0.022097086912079608f;  // 1/sqrt(2048)
#pragma unroll
        for (int i = 0; i < 4; i++) {
            const int q = tq + i;
#pragma unroll
            for (int j = 0; j < 8; j++) {
                const int k = tk + j;
                Ps[q * P_PAD + k] = (k <= q) ? acc[i][j] * scale : -1e30f;
            }
        }
    }
    __syncthreads();

    // column softmax over q (axis=-2), valid q in [k, 63]
    if (tid < SEQ) {
        const int k = tid;
        float m = -1e30f;
        for (int q = k; q < SEQ; q++) m = fmaxf(m, Ps[q * P_PAD + k]);
        float ssum = 0.0f;
        for (int q = k; q < SEQ; q++) {
            float e = __expf(Ps[q * P_PAD + k] - m);
            Ps[q * P_PAD + k] = e;
            ssum += e;
        }
        const float inv = 1.0f / ssum;
        for (int q = 0; q < SEQ; q++)
            Ps[q * P_PAD + k] = (q < k) ? 0.0f : Ps[q * P_PAD + k] * inv;
    }
    __syncthreads();

    // PV: thread computes 8q x 8c
    {
        const int tq = (tid >> 4) * 8;
        const int tc = (tid & 15) * 8;
        float acc[8][8];
#pragma unroll
        for (int i = 0; i < 8; i++)
#pragma unroll
            for (int j = 0; j < 8; j++) acc[i][j] = 0.0f;

        for (int k = 0; k < SEQ; k++) {
            float pv[8], vv[8];
#pragma unroll
            for (int i = 0; i < 8; i++) pv[i] = Ps[(tq + i) * P_PAD + k];
            *(float4*)(vv)     = *(const float4*)&Vs[k * V_PAD + tc];
            *(float4*)(vv + 4) = *(const float4*)&Vs[k * V_PAD + tc + 4];
#pragma unroll
            for (int i = 0; i < 8; i++)
#pragma unroll
                for (int j = 0; j < 8; j++)
                    acc[i][j] = fmaf(pv[i], vv[j], acc[i][j]);
        }

        float* outp = att + (size_t)b * SEQ * DMODEL + h * HD;
#pragma unroll
        for (int i = 0; i < 8; i++)
#pragma unroll
            for (int j = 0; j < 8; j++)
                outp[(size_t)(tq + i) * DMODEL + tc + j] = round_tf32(acc[i][j]);
    }
}

// ---------------------------------------------------------------------------
// Launch
// ---------------------------------------------------------------------------
extern "C" void kernel_launch(void* const* d_in, const int* in_sizes, int n_in,
                              void* d_out, int out_size)
{
    const float* x     = (const float*)d_in[0];
    const float* W_qkv = (const float*)d_in[1];
    const float* b_qkv = (const float*)d_in[2];
    const float* W_out = (const float*)d_in[3];
    const float* b_out = (const float*)d_in[4];
    float* out = (float*)d_out;

    float *qkv = nullptr, *att = nullptr, *xr = nullptr, *wqr = nullptr, *wor = nullptr;
    cudaGetSymbolAddress((void**)&qkv, g_qkv);
    cudaGetSymbolAddress((void**)&att, g_att);
    cudaGetSymbolAddress((void**)&xr,  g_xr);
    cudaGetSymbolAddress((void**)&wqr, g_wqr);
    cudaGetSymbolAddress((void**)&wor, g_wor);

    cudaFuncSetAttribute(gemm_nt_tc, cudaFuncAttributeMaxDynamicSharedMemorySize, GEMM_SMEM);
    cudaFuncSetAttribute(attn64, cudaFuncAttributeMaxDynamicSharedMemorySize, ATTN_SMEM_BYTES);

    // 0) unbiased tf32 rounding of GEMM inputs
    {
        int n4x = TOK * DMODEL / 4;
        round_tf32_kernel<<<n4x / 256, 256>>>((const float4*)x, (float4*)xr, n4x);
        int n4q = E3 * DMODEL / 4;
        round_tf32_kernel<<<n4q / 256, 256>>>((const float4*)W_qkv, (float4*)wqr, n4q);
        int n4o = DMODEL * DMODEL / 4;
        round_tf32_kernel<<<n4o / 256, 256>>>((const float4*)W_out, (float4*)wor, n4o);
    }

    // 1) qkv = x @ W_qkv^T + b_qkv   [16384, 6144]
    {
        dim3 grid(E3 / BN, TOK / BM);   // 48 x 128
        gemm_nt_tc<<<grid, 128, GEMM_SMEM>>>(xr, wqr, b_qkv, qkv, TOK, E3, DMODEL);
    }

    // 2) attention per (b, h)
    {
        attn64<<<NBATCH * NHEAD, 128, ATTN_SMEM_BYTES>>>(qkv, att);
    }

    // 3) out = att @ W_out^T + b_out  [16384, 2048]
    {
        dim3 grid(DMODEL / BN, TOK / BM);   // 16 x 128
        gemm_nt_tc<<<grid, 128, GEMM_SMEM>>>(att, wor, b_out, out, TOK, DMODEL, DMODEL);
    }
}

// round 10
// speedup vs baseline: 1.8038x; 1.7318x over previous
#include <cuda_runtime.h>
#include <cuda_fp16.h>
#include <stdint.h>
#include <math.h>

// ---------------------------------------------------------------------------
// Problem constants
// ---------------------------------------------------------------------------
#define TOK      16384
#define DMODEL   2048
#define E3       6144
#define NHEAD    16
#define HD       128
#define SEQ      64
#define NBATCH   256

// Scratch (device globals: allocation rules forbid cudaMalloc)
__device__ float  g_qkv[(size_t)TOK * E3];          // fp32 qkv (GEMM1 out)
__device__ __half g_att[(size_t)TOK * DMODEL];      // attention out, fp16
__device__ __half g_xh [(size_t)TOK * DMODEL];      // x -> fp16
__device__ __half g_wqh[(size_t)E3  * DMODEL];      // W_qkv -> fp16
__device__ __half g_woh[(size_t)DMODEL * DMODEL];   // W_out -> fp16

// ---------------------------------------------------------------------------
// fp32 -> fp16 (rn) conversion
// ---------------------------------------------------------------------------
__global__ void __launch_bounds__(256)
f2h_kernel(const float4* __restrict__ in, uint2* __restrict__ out, int n4)
{
    int i = blockIdx.x * blockDim.x + threadIdx.x;
    if (i < n4) {
        float4 v = in[i];
        __half2 h0 = __floats2half2_rn(v.x, v.y);
        __half2 h1 = __floats2half2_rn(v.z, v.w);
        uint2 u;
        u.x = *(uint32_t*)&h0;
        u.y = *(uint32_t*)&h1;
        out[i] = u;
    }
}

// ---------------------------------------------------------------------------
// FP16 tensor-core NT GEMM: C[M,N] = A[M,K] @ B[N,K]^T + bias[N]   (fp32 acc)
// CTA tile 128x128, BK=64 fp16, 3-stage cp.async, one barrier per k-iter.
// 128 threads = 4 warps (2m x 2n), warp tile 64x64:
//   per k16-step 8 ldmatrix.x4 feed 32 m16n8k16 MMAs.
// Smem rows: 64 fp16 data + 8 pad = 144B -> conflict-free ldmatrix
//   (phase banks 36*r + 8*k mod 32 all distinct).
// smem 110KB -> 2 CTAs/SM.
// ---------------------------------------------------------------------------
#define BM 128
#define BN 128
#define BK 64
#define STAGES 3
#define LDH 72                                        // fp16 per row (64+8 pad)
#define ROWB 144                                      // bytes per row
#define STAGE_BYTES (BM * ROWB)                       // 18432
#define GEMM_SMEM   (STAGES * STAGE_BYTES * 2)        // 110592

__device__ __forceinline__ void cp16(uint32_t dst, const __half* src) {
    asm volatile("cp.async.cg.shared.global [%0], [%1], 16;\n" :: "r"(dst), "l"(src));
}
__device__ __forceinline__ void cp_commit() {
    asm volatile("cp.async.commit_group;\n");
}
__device__ __forceinline__ void ldsm4(uint32_t (&r)[4], uint32_t addr) {
    asm volatile("ldmatrix.sync.aligned.m8n8.x4.shared.b16 {%0,%1,%2,%3}, [%4];\n"
                 : "=r"(r[0]), "=r"(r[1]), "=r"(r[2]), "=r"(r[3]) : "r"(addr));
}
__device__ __forceinline__ void mma_f16(float (&c)[4], const uint32_t (&a)[4],
                                        uint32_t b0, uint32_t b1) {
    asm volatile(
        "mma.sync.aligned.m16n8k16.row.col.f32.f16.f16.f32 "
        "{%0,%1,%2,%3},{%4,%5,%6,%7},{%8,%9},{%0,%1,%2,%3};\n"
        : "+f"(c[0]), "+f"(c[1]), "+f"(c[2]), "+f"(c[3])
        : "r"(a[0]), "r"(a[1]), "r"(a[2]), "r"(a[3]), "r"(b0), "r"(b1));
}

__global__ void __launch_bounds__(128, 2)
gemm_nt_f16(const __half* __restrict__ A, const __half* __restrict__ Bm,
            const float* __restrict__ bias, float* __restrict__ C,
            int M, int N, int K)
{
    extern __shared__ char smc[];
    const uint32_t smA = (uint32_t)__cvta_generic_to_shared(smc);
    const uint32_t smB = smA + STAGES * STAGE_BYTES;

    const int tid  = threadIdx.x;
    const int bm   = blockIdx.y * BM;
    const int bn   = blockIdx.x * BN;
    const int warp = tid >> 5;
    const int lane = tid & 31;
    const int wm   = warp >> 1;   // 0..1
    const int wn   = warp & 1;    // 0..1

    // gmem->smem: per stage per matrix 128 rows x 8 chunks(16B) = 1024 chunks;
    // 128 threads -> 8 chunks each (A and B).
    const __half* AgP[8]; uint32_t sAP[8];
    const __half* BgP[8]; uint32_t sBP[8];
#pragma unroll
    for (int i = 0; i < 8; i++) {
        const int c   = tid + i * 128;   // 0..1023
        const int row = c >> 3;          // 0..127
        const int ch  = c & 7;           // 16B chunk in row
        AgP[i] = A  + (size_t)(bm + row) * K + ch * 8;
        BgP[i] = Bm + (size_t)(bn + row) * K + ch * 8;
        sAP[i] = smA + (uint32_t)(row * ROWB + ch * 16);
        sBP[i] = smB + (uint32_t)(row * ROWB + ch * 16);
    }

    // ldmatrix per-lane fragment bases: lanes 0-15 -> rows, lanes 16-31 -> +8 fp16 in k
    const int lrow = lane & 15;
    const int lkb  = (lane >> 4) * 16;   // byte offset within k16 block
    const uint32_t aFrag = smA + (uint32_t)((wm * 64 + lrow) * ROWB + lkb);
    const uint32_t bFrag = smB + (uint32_t)((wn * 64 + lrow) * ROWB + lkb);

    float c[4][8][4];
#pragma unroll
    for (int i = 0; i < 4; i++)
#pragma unroll
        for (int j = 0; j < 8; j++)
#pragma unroll
            for (int r = 0; r < 4; r++) c[i][j][r] = 0.0f;

    const int NT = K / BK;   // 32

    // prologue
#pragma unroll
    for (int p = 0; p < STAGES - 1; p++) {
        const int koff = p * BK;
        const uint32_t so = (uint32_t)(p * STAGE_BYTES);
#pragma unroll
        for (int i = 0; i < 8; i++) {
            cp16(sAP[i] + so, AgP[i] + koff);
            cp16(sBP[i] + so, BgP[i] + koff);
        }
        cp_commit();
    }

    int st = 0;
    for (int s = 0; s < NT; s++) {
        if (s + 1 < NT) {
            asm volatile("cp.async.wait_group 1;\n");
        } else {
            asm volatile("cp.async.wait_group 0;\n");
        }
        __syncthreads();

        // prefetch next stage into the slot freed by stage s-1
        if (s + STAGES - 1 < NT) {
            const int koff = (s + STAGES - 1) * BK;
            const int slot = (s + STAGES - 1) % STAGES;
            const uint32_t so = (uint32_t)(slot * STAGE_BYTES);
#pragma unroll
            for (int i = 0; i < 8; i++) {
                cp16(sAP[i] + so, AgP[i] + koff);
                cp16(sBP[i] + so, BgP[i] + koff);
            }
            cp_commit();
        }

        // compute stage st: 4 k16-steps, 32 MMAs each
        {
            const uint32_t aOff = aFrag + (uint32_t)(st * STAGE_BYTES);
            const uint32_t bOff = bFrag + (uint32_t)(st * STAGE_BYTES);
#pragma unroll
            for (int kk = 0; kk < 4; kk++) {
                uint32_t a[4][4];
#pragma unroll
                for (int am = 0; am < 4; am++)
                    ldsm4(a[am], aOff + kk * 32 + am * (16 * ROWB));
                uint32_t b[4][4];
#pragma unroll
                for (int pr = 0; pr < 4; pr++)
                    ldsm4(b[pr], bOff + kk * 32 + pr * (16 * ROWB));
#pragma unroll
                for (int am = 0; am < 4; am++)
#pragma unroll
                    for (int an = 0; an < 8; an++)
                        mma_f16(c[am][an], a[am],
                                b[an >> 1][an & 1], b[an >> 1][2 + (an & 1)]);
            }
        }
        st = (st + 1 == STAGES) ? 0 : st + 1;
    }

    // epilogue
    const int erow = lane >> 2;
    const int ecol = (lane & 3) * 2;
#pragma unroll
    for (int am = 0; am < 4; am++) {
        const int row = bm + wm * 64 + am * 16 + erow;
#pragma unroll
        for (int an = 0; an < 8; an++) {
            const int col = bn + wn * 64 + an * 8 + ecol;
            const float b0v = __ldg(bias + col);
            const float b1v = __ldg(bias + col + 1);
            float* p0 = C + (size_t)row * N + col;
            float* p1 = C + (size_t)(row + 8) * N + col;
            p0[0] = c[am][an][0] + b0v;
            p0[1] = c[am][an][1] + b1v;
            p1[0] = c[am][an][2] + b0v;
            p1[1] = c[am][an][3] + b1v;
        }
    }
}

// ---------------------------------------------------------------------------
// Attention per (batch, head): K/V/P in smem, Q streamed via L1.
// fp32 math; output written as fp16 (rn) for GEMM3.
// ---------------------------------------------------------------------------
#define K_PAD 129
#define V_PAD 132
#define P_PAD 65
#define ATTN_SMEM_FLOATS (SEQ * K_PAD + SEQ * V_PAD + SEQ * P_PAD)
#define ATTN_SMEM_BYTES  (ATTN_SMEM_FLOATS * 4)

__global__ void __launch_bounds__(128)
attn64(const float* __restrict__ qkv, __half* __restrict__ att)
{
    extern __shared__ float smn[];
    float* Ks = smn;
    float* Vs = Ks + SEQ * K_PAD;
    float* Ps = Vs + SEQ * V_PAD;

    const int bh  = blockIdx.x;
    const int b   = bh >> 4;
    const int h   = bh & 15;
    const int tid = threadIdx.x;

    const float* base = qkv + (size_t)b * SEQ * E3 + h * HD;

    // load K, V tiles (2 threads per row, 64 floats each)
    {
        const int r  = tid >> 1;
        const int cp = (tid & 1) * 64;
        const float* src = base + (size_t)r * E3 + cp;
        float* dk = Ks + r * K_PAD + cp;
        float* dv = Vs + r * V_PAD + cp;
#pragma unroll
        for (int i = 0; i < 64; i += 4) {
            float4 k4 = *(const float4*)(src + DMODEL + i);
            float4 v4 = *(const float4*)(src + 2 * DMODEL + i);
            dk[i] = k4.x; dk[i+1] = k4.y; dk[i+2] = k4.z; dk[i+3] = k4.w;
            *(float4*)(dv + i) = v4;
        }
    }
    __syncthreads();

    // scores: thread computes 4q x 8k, Q from gmem (L1)
    {
        const int tq = (tid >> 3) * 4;
        const int tk = (tid & 7) * 8;
        const float* q0 = base + (size_t)(tq + 0) * E3;
        const float* q1 = base + (size_t)(tq + 1) * E3;
        const float* q2 = base + (size_t)(tq + 2) * E3;
        const float* q3 = base + (size_t)(tq + 3) * E3;
        float acc[4][8];
#pragma unroll
        for (int i = 0; i < 4; i++)
#pragma unroll
            for (int j = 0; j < 8; j++) acc[i][j] = 0.0f;

        for (int kd = 0; kd < HD; kd += 4) {
            float qv[4][4];
            *(float4*)qv[0] = __ldg((const float4*)(q0 + kd));
            *(float4*)qv[1] = __ldg((const float4*)(q1 + kd));
            *(float4*)qv[2] = __ldg((const float4*)(q2 + kd));
            *(float4*)qv[3] = __ldg((const float4*)(q3 + kd));
#pragma unroll
            for (int kk = 0; kk < 4; kk++) {
                float kv[8];
#pragma unroll
                for (int j = 0; j < 8; j++) kv[j] = Ks[(tk + j) * K_PAD + kd + kk];
#pragma unroll
                for (int i = 0; i < 4; i++)
#pragma unroll
                    for (int j = 0; j < 8; j++)
                        acc[i][j] = fmaf(qv[i][kk], kv[j], acc[i][j]);
            }
        }

        const float scale = 0.022097086912079608f;  // 1/sqrt(2048)
#pragma unroll
        for (int i = 0; i < 4; i++) {
            const int q = tq + i;
#pragma unroll
            for (int j = 0; j < 8; j++) {
                const int k = tk + j;
                Ps[q * P_PAD + k] = (k <= q) ? acc[i][j] * scale : -1e30f;
            }
        }
    }
    __syncthreads();

    // column softmax over q (axis=-2), valid q in [k, 63]
    if (tid < SEQ) {
        const int k = tid;
        float m = -1e30f;
        for (int q = k; q < SEQ; q++) m = fmaxf(m, Ps[q * P_PAD + k]);
        float ssum = 0.0f;
        for (int q = k; q < SEQ; q++) {
            float e = __expf(Ps[q * P_PAD + k] - m);
            Ps[q * P_PAD + k] = e;
            ssum += e;
        }
        const float inv = 1.0f / ssum;
        for (int q = 0; q < SEQ; q++)
            Ps[q * P_PAD + k] = (q < k) ? 0.0f : Ps[q * P_PAD + k] * inv;
    }
    __syncthreads();

    // PV: thread computes 8q x 8c; write fp16
    {
        const int tq = (tid >> 4) * 8;
        const int tc = (tid & 15) * 8;
        float acc[8][8];
#pragma unroll
        for (int i = 0; i < 8; i++)
#pragma unroll
            for (int j = 0; j < 8; j++) acc[i][j] = 0.0f;

        for (int k = 0; k < SEQ; k++) {
            float pv[8], vv[8];
#pragma unroll
            for (int i = 0; i < 8; i++) pv[i] = Ps[(tq + i) * P_PAD + k];
            *(float4*)(vv)     = *(const float4*)&Vs[k * V_PAD + tc];
            *(float4*)(vv + 4) = *(const float4*)&Vs[k * V_PAD + tc + 4];
#pragma unroll
            for (int i = 0; i < 8; i++)
#pragma unroll
                for (int j = 0; j < 8; j++)
                    acc[i][j] = fmaf(pv[i], vv[j], acc[i][j]);
        }

        __half* outp = att + (size_t)b * SEQ * DMODEL + h * HD;
#pragma unroll
        for (int i = 0; i < 8; i++) {
            __half2 hs[4];
#pragma unroll
            for (int j = 0; j < 4; j++)
                hs[j] = __floats2half2_rn(acc[i][2*j], acc[i][2*j+1]);
            *(uint2*)(outp + (size_t)(tq + i) * DMODEL + tc) =
                *(uint2*)&hs[0];
            *(uint2*)(outp + (size_t)(tq + i) * DMODEL + tc + 4) =
                *(uint2*)&hs[2];
        }
    }
}

// ---------------------------------------------------------------------------
// Launch
// ---------------------------------------------------------------------------
extern "C" void kernel_launch(void* const* d_in, const int* in_sizes, int n_in,
                              void* d_out, int out_size)
{
    const float* x     = (const float*)d_in[0];
    const float* W_qkv = (const float*)d_in[1];
    const float* b_qkv = (const float*)d_in[2];
    const float* W_out = (const float*)d_in[3];
    const float* b_out = (const float*)d_in[4];
    float* out = (float*)d_out;

    float*  qkv = nullptr;
    __half* att = nullptr;
    __half* xh  = nullptr;
    __half* wqh = nullptr;
    __half* woh = nullptr;
    cudaGetSymbolAddress((void**)&qkv, g_qkv);
    cudaGetSymbolAddress((void**)&att, g_att);
    cudaGetSymbolAddress((void**)&xh,  g_xh);
    cudaGetSymbolAddress((void**)&wqh, g_wqh);
    cudaGetSymbolAddress((void**)&woh, g_woh);

    cudaFuncSetAttribute(gemm_nt_f16, cudaFuncAttributeMaxDynamicSharedMemorySize, GEMM_SMEM);
    cudaFuncSetAttribute(attn64, cudaFuncAttributeMaxDynamicSharedMemorySize, ATTN_SMEM_BYTES);

    // 0) fp32 -> fp16 (rn) conversions of GEMM inputs
    {
        int n4x = TOK * DMODEL / 4;
        f2h_kernel<<<n4x / 256, 256>>>((const float4*)x, (uint2*)xh, n4x);
        int n4q = E3 * DMODEL / 4;
        f2h_kernel<<<n4q / 256, 256>>>((const float4*)W_qkv, (uint2*)wqh, n4q);
        int n4o = DMODEL * DMODEL / 4;
        f2h_kernel<<<n4o / 256, 256>>>((const float4*)W_out, (uint2*)woh, n4o);
    }

    // 1) qkv = x @ W_qkv^T + b_qkv   [16384, 6144]
    {
        dim3 grid(E3 / BN, TOK / BM);   // 48 x 128
        gemm_nt_f16<<<grid, 128, GEMM_SMEM>>>(xh, wqh, b_qkv, qkv, TOK, E3, DMODEL);
    }

    // 2) attention per (b, h) — fp32 math, fp16 output
    {
        attn64<<<NBATCH * NHEAD, 128, ATTN_SMEM_BYTES>>>(qkv, att);
    }

    // 3) out = att @ W_out^T + b_out  [16384, 2048]
    {
        dim3 grid(DMODEL / BN, TOK / BM);   // 16 x 128
        gemm_nt_f16<<<grid, 128, GEMM_SMEM>>>(att, woh, b_out, out, TOK, DMODEL, DMODEL);
    }
}

// round 11
// speedup vs baseline: 2.2060x; 1.2230x over previous
#include <cuda_runtime.h>
#include <cuda_fp16.h>
#include <stdint.h>
#include <math.h>

// ---------------------------------------------------------------------------
// Problem constants
// ---------------------------------------------------------------------------
#define TOK      16384
#define DMODEL   2048
#define E3       6144
#define NHEAD    16
#define HD       128
#define SEQ      64
#define NBATCH   256

// Scratch (device globals: allocation rules forbid cudaMalloc)
__device__ __half g_qkvh[(size_t)TOK * E3];         // GEMM1 out, fp16
__device__ __half g_att[(size_t)TOK * DMODEL];      // attention out, fp16
__device__ __half g_xh [(size_t)TOK * DMODEL];      // x -> fp16
__device__ __half g_wqh[(size_t)E3  * DMODEL];      // W_qkv -> fp16
__device__ __half g_woh[(size_t)DMODEL * DMODEL];   // W_out -> fp16

// ---------------------------------------------------------------------------
// fp32 -> fp16 (rn) conversion
// ---------------------------------------------------------------------------
__global__ void __launch_bounds__(256)
f2h_kernel(const float4* __restrict__ in, uint2* __restrict__ out, int n4)
{
    int i = blockIdx.x * blockDim.x + threadIdx.x;
    if (i < n4) {
        float4 v = in[i];
        __half2 h0 = __floats2half2_rn(v.x, v.y);
        __half2 h1 = __floats2half2_rn(v.z, v.w);
        uint2 u;
        u.x = *(uint32_t*)&h0;
        u.y = *(uint32_t*)&h1;
        out[i] = u;
    }
}

// ---------------------------------------------------------------------------
// Common PTX helpers
// ---------------------------------------------------------------------------
__device__ __forceinline__ void cp16(uint32_t dst, const __half* src) {
    asm volatile("cp.async.cg.shared.global [%0], [%1], 16;\n" :: "r"(dst), "l"(src));
}
__device__ __forceinline__ void cp_commit() {
    asm volatile("cp.async.commit_group;\n");
}
__device__ __forceinline__ void ldsm4(uint32_t (&r)[4], uint32_t addr) {
    asm volatile("ldmatrix.sync.aligned.m8n8.x4.shared.b16 {%0,%1,%2,%3}, [%4];\n"
                 : "=r"(r[0]), "=r"(r[1]), "=r"(r[2]), "=r"(r[3]) : "r"(addr));
}
__device__ __forceinline__ void ldsm4t(uint32_t (&r)[4], uint32_t addr) {
    asm volatile("ldmatrix.sync.aligned.m8n8.x4.trans.shared.b16 {%0,%1,%2,%3}, [%4];\n"
                 : "=r"(r[0]), "=r"(r[1]), "=r"(r[2]), "=r"(r[3]) : "r"(addr));
}
__device__ __forceinline__ void mma_f16(float (&c)[4], const uint32_t (&a)[4],
                                        uint32_t b0, uint32_t b1) {
    asm volatile(
        "mma.sync.aligned.m16n8k16.row.col.f32.f16.f16.f32 "
        "{%0,%1,%2,%3},{%4,%5,%6,%7},{%8,%9},{%0,%1,%2,%3};\n"
        : "+f"(c[0]), "+f"(c[1]), "+f"(c[2]), "+f"(c[3])
        : "r"(a[0]), "r"(a[1]), "r"(a[2]), "r"(a[3]), "r"(b0), "r"(b1));
}

// ---------------------------------------------------------------------------
// FP16 tensor-core NT GEMM: C[M,N] = A[M,K] @ B[N,K]^T + bias[N]   (fp32 acc)
// CTA tile 128x128, BK=64 fp16, 3-stage cp.async, one barrier per k-iter.
// 128 threads = 4 warps (2m x 2n), warp tile 64x64.
// Smem rows: 64 fp16 + 8 pad = 144B -> conflict-free ldmatrix.
// HOUT: write C as fp16 (half2) instead of fp32.
// ---------------------------------------------------------------------------
#define BM 128
#define BN 128
#define BK 64
#define STAGES 3
#define ROWB 144
#define STAGE_BYTES (BM * ROWB)                       // 18432
#define GEMM_SMEM   (STAGES * STAGE_BYTES * 2)        // 110592

template<bool HOUT>
__global__ void __launch_bounds__(128, 2)
gemm_nt_f16(const __half* __restrict__ A, const __half* __restrict__ Bm,
            const float* __restrict__ bias, void* __restrict__ Cv,
            int M, int N, int K)
{
    extern __shared__ char smc[];
    const uint32_t smA = (uint32_t)__cvta_generic_to_shared(smc);
    const uint32_t smB = smA + STAGES * STAGE_BYTES;

    const int tid  = threadIdx.x;
    const int bm   = blockIdx.y * BM;
    const int bn   = blockIdx.x * BN;
    const int warp = tid >> 5;
    const int lane = tid & 31;
    const int wm   = warp >> 1;
    const int wn   = warp & 1;

    const __half* AgP[8]; uint32_t sAP[8];
    const __half* BgP[8]; uint32_t sBP[8];
#pragma unroll
    for (int i = 0; i < 8; i++) {
        const int c   = tid + i * 128;
        const int row = c >> 3;
        const int ch  = c & 7;
        AgP[i] = A  + (size_t)(bm + row) * K + ch * 8;
        BgP[i] = Bm + (size_t)(bn + row) * K + ch * 8;
        sAP[i] = smA + (uint32_t)(row * ROWB + ch * 16);
        sBP[i] = smB + (uint32_t)(row * ROWB + ch * 16);
    }

    const int lrow = lane & 15;
    const int lkb  = (lane >> 4) * 16;
    const uint32_t aFrag = smA + (uint32_t)((wm * 64 + lrow) * ROWB + lkb);
    const uint32_t bFrag = smB + (uint32_t)((wn * 64 + lrow) * ROWB + lkb);

    float c[4][8][4];
#pragma unroll
    for (int i = 0; i < 4; i++)
#pragma unroll
        for (int j = 0; j < 8; j++)
#pragma unroll
            for (int r = 0; r < 4; r++) c[i][j][r] = 0.0f;

    const int NT = K / BK;

#pragma unroll
    for (int p = 0; p < STAGES - 1; p++) {
        const int koff = p * BK;
        const uint32_t so = (uint32_t)(p * STAGE_BYTES);
#pragma unroll
        for (int i = 0; i < 8; i++) {
            cp16(sAP[i] + so, AgP[i] + koff);
            cp16(sBP[i] + so, BgP[i] + koff);
        }
        cp_commit();
    }

    int st = 0;
    for (int s = 0; s < NT; s++) {
        if (s + 1 < NT) {
            asm volatile("cp.async.wait_group 1;\n");
        } else {
            asm volatile("cp.async.wait_group 0;\n");
        }
        __syncthreads();

        if (s + STAGES - 1 < NT) {
            const int koff = (s + STAGES - 1) * BK;
            const int slot = (s + STAGES - 1) % STAGES;
            const uint32_t so = (uint32_t)(slot * STAGE_BYTES);
#pragma unroll
            for (int i = 0; i < 8; i++) {
                cp16(sAP[i] + so, AgP[i] + koff);
                cp16(sBP[i] + so, BgP[i] + koff);
            }
            cp_commit();
        }

        {
            const uint32_t aOff = aFrag + (uint32_t)(st * STAGE_BYTES);
            const uint32_t bOff = bFrag + (uint32_t)(st * STAGE_BYTES);
#pragma unroll
            for (int kk = 0; kk < 4; kk++) {
                uint32_t a[4][4];
#pragma unroll
                for (int am = 0; am < 4; am++)
                    ldsm4(a[am], aOff + kk * 32 + am * (16 * ROWB));
                uint32_t b[4][4];
#pragma unroll
                for (int pr = 0; pr < 4; pr++)
                    ldsm4(b[pr], bOff + kk * 32 + pr * (16 * ROWB));
#pragma unroll
                for (int am = 0; am < 4; am++)
#pragma unroll
                    for (int an = 0; an < 8; an++)
                        mma_f16(c[am][an], a[am],
                                b[an >> 1][an & 1], b[an >> 1][2 + (an & 1)]);
            }
        }
        st = (st + 1 == STAGES) ? 0 : st + 1;
    }

    // epilogue
    const int erow = lane >> 2;
    const int ecol = (lane & 3) * 2;
#pragma unroll
    for (int am = 0; am < 4; am++) {
        const int row = bm + wm * 64 + am * 16 + erow;
#pragma unroll
        for (int an = 0; an < 8; an++) {
            const int col = bn + wn * 64 + an * 8 + ecol;
            const float b0v = __ldg(bias + col);
            const float b1v = __ldg(bias + col + 1);
            if (HOUT) {
                __half* C = (__half*)Cv;
                __half2 v0 = __floats2half2_rn(c[am][an][0] + b0v, c[am][an][1] + b1v);
                __half2 v1 = __floats2half2_rn(c[am][an][2] + b0v, c[am][an][3] + b1v);
                *(__half2*)(C + (size_t)row * N + col) = v0;
                *(__half2*)(C + (size_t)(row + 8) * N + col) = v1;
            } else {
                float* C = (float*)Cv;
                float* p0 = C + (size_t)row * N + col;
                float* p1 = C + (size_t)(row + 8) * N + col;
                p0[0] = c[am][an][0] + b0v;
                p0[1] = c[am][an][1] + b1v;
                p1[0] = c[am][an][2] + b0v;
                p1[1] = c[am][an][3] + b1v;
            }
        }
    }
}

// ---------------------------------------------------------------------------
// Tensor-core attention per (batch, head). 128 threads = 4 warps.
//  - Q/K/V fp16 tiles 64x128 in smem (rows 256B + 16B pad = 272B)
//  - QK^T via m16n8k16 (warp w -> q rows 16w..16w+15), fp32 scores
//  - column softmax (axis=-2) in fp32
//  - P -> fp16 (reuses Q smem region), PV via mma with ldmatrix.trans on V
// ---------------------------------------------------------------------------
#define QROWB 272
#define PROWB 144
#define PS_PAD 65
#define OFF_Q 0
#define OFF_K 17408
#define OFF_V 34816
#define OFF_P 52224
#define ATTN_SMEM (OFF_P + SEQ * PS_PAD * 4)   // 68864

__global__ void __launch_bounds__(128)
attn64(const __half* __restrict__ qkv, __half* __restrict__ att)
{
    extern __shared__ char smc[];
    const uint32_t sb  = (uint32_t)__cvta_generic_to_shared(smc);
    const uint32_t smQ = sb + OFF_Q;
    const uint32_t smK = sb + OFF_K;
    const uint32_t smV = sb + OFF_V;
    float* Ps = (float*)(smc + OFF_P);

    const int bh   = blockIdx.x;
    const int b    = bh >> 4;
    const int h    = bh & 15;
    const int tid  = threadIdx.x;
    const int warp = tid >> 5;
    const int lane = tid & 31;

    const __half* base = qkv + (size_t)b * SEQ * E3 + h * HD;

    // ---- load Q, K, V tiles: 64 rows x 16 chunks(16B) each ----
#pragma unroll
    for (int i = 0; i < 8; i++) {
        const int c   = tid + i * 128;  // 0..1023
        const int row = c >> 4;
        const int ch  = c & 15;
        const __half* src = base + (size_t)row * E3 + ch * 8;
        const uint32_t d  = (uint32_t)(row * QROWB + ch * 16);
        cp16(smQ + d, src);
        cp16(smK + d, src + DMODEL);
        cp16(smV + d, src + 2 * DMODEL);
    }
    cp_commit();
    asm volatile("cp.async.wait_group 0;\n");
    __syncthreads();

    const int lrow = lane & 15;
    const int lkb  = (lane >> 4) * 16;
    const int erow = lane >> 2;
    const int ecol = (lane & 3) * 2;

    // ---- QK^T: warp w computes q rows 16w..16w+15, all 64 k cols ----
    {
        const uint32_t aBase = smQ + (uint32_t)((warp * 16 + lrow) * QROWB + lkb);
        float scc[8][4];
#pragma unroll
        for (int j = 0; j < 8; j++)
#pragma unroll
            for (int r = 0; r < 4; r++) scc[j][r] = 0.0f;

#pragma unroll
        for (int kk = 0; kk < 8; kk++) {
            uint32_t a[4];
            ldsm4(a, aBase + kk * 32);
            uint32_t bb[4][4];
#pragma unroll
            for (int pr = 0; pr < 4; pr++)
                ldsm4(bb[pr], smK + (uint32_t)((pr * 16 + lrow) * QROWB + lkb) + kk * 32);
#pragma unroll
            for (int an = 0; an < 8; an++)
                mma_f16(scc[an], a, bb[an >> 1][an & 1], bb[an >> 1][2 + (an & 1)]);
        }

        const float scale = 0.022097086912079608f;  // 1/sqrt(2048)
#pragma unroll
        for (int an = 0; an < 8; an++) {
            const int q0 = warp * 16 + erow;
            const int q1 = q0 + 8;
            const int k0 = an * 8 + ecol;
            Ps[q0 * PS_PAD + k0]     = (k0     <= q0) ? scc[an][0] * scale : -1e30f;
            Ps[q0 * PS_PAD + k0 + 1] = (k0 + 1 <= q0) ? scc[an][1] * scale : -1e30f;
            Ps[q1 * PS_PAD + k0]     = (k0     <= q1) ? scc[an][2] * scale : -1e30f;
            Ps[q1 * PS_PAD + k0 + 1] = (k0 + 1 <= q1) ? scc[an][3] * scale : -1e30f;
        }
    }
    __syncthreads();

    // ---- column softmax over q (axis=-2), valid q in [k, 63] ----
    if (tid < SEQ) {
        const int k = tid;
        float m = -1e30f;
        for (int q = k; q < SEQ; q++) m = fmaxf(m, Ps[q * PS_PAD + k]);
        float ssum = 0.0f;
        for (int q = k; q < SEQ; q++) {
            float e = __expf(Ps[q * PS_PAD + k] - m);
            Ps[q * PS_PAD + k] = e;
            ssum += e;
        }
        const float inv = 1.0f / ssum;
        for (int q = 0; q < SEQ; q++)
            Ps[q * PS_PAD + k] = (q < k) ? 0.0f : Ps[q * PS_PAD + k] * inv;
    }
    __syncthreads();

    // ---- P -> fp16 into Ph (reuse Q region; rows 128B + 16B pad) ----
    {
        const int r  = tid >> 1;
        const int cb = (tid & 1) * 32;
#pragma unroll
        for (int j = 0; j < 32; j += 2) {
            __half2 hp = __floats2half2_rn(Ps[r * PS_PAD + cb + j],
                                           Ps[r * PS_PAD + cb + j + 1]);
            *(__half2*)(smc + OFF_Q + r * PROWB + (cb + j) * 2) = hp;
        }
    }
    __syncthreads();

    // ---- PV: out[q, c] = sum_k P[q,k] * V[k,c]; V via ldmatrix.trans ----
    {
        const uint32_t aBase = smQ + (uint32_t)((warp * 16 + lrow) * PROWB + lkb);
        // trans fragment address: mat = lane>>3: khalf=(lane>>4)&1, nhalf=(lane>>3)&1
        const int vrow_off = ((lane >> 4) & 1) * 8 + (lane & 7);
        const int vcol_off = ((lane >> 3) & 1) * 8;

        float pacc[16][4];
#pragma unroll
        for (int j = 0; j < 16; j++)
#pragma unroll
            for (int r = 0; r < 4; r++) pacc[j][r] = 0.0f;

#pragma unroll
        for (int kk = 0; kk < 4; kk++) {
            uint32_t a[4];
            ldsm4(a, aBase + kk * 32);
#pragma unroll
            for (int g = 0; g < 8; g++) {
                uint32_t vb[4];
                ldsm4t(vb, smV + (uint32_t)((kk * 16 + vrow_off) * QROWB
                                            + (g * 16 + vcol_off) * 2));
                mma_f16(pacc[2 * g],     a, vb[0], vb[2]);
                mma_f16(pacc[2 * g + 1], a, vb[1], vb[3]);
            }
        }

        __half* outp = att + (size_t)b * SEQ * DMODEL + h * HD;
        const int q0 = warp * 16 + erow;
        const int q1 = q0 + 8;
#pragma unroll
        for (int at = 0; at < 16; at++) {
            const int c0 = (at >> 1) * 16 + (at & 1) * 8 + ecol;
            __half2 v0 = __floats2half2_rn(pacc[at][0], pacc[at][1]);
            __half2 v1 = __floats2half2_rn(pacc[at][2], pacc[at][3]);
            *(__half2*)(outp + (size_t)q0 * DMODEL + c0) = v0;
            *(__half2*)(outp + (size_t)q1 * DMODEL + c0) = v1;
        }
    }
}

// ---------------------------------------------------------------------------
// Launch
// ---------------------------------------------------------------------------
extern "C" void kernel_launch(void* const* d_in, const int* in_sizes, int n_in,
                              void* d_out, int out_size)
{
    const float* x     = (const float*)d_in[0];
    const float* W_qkv = (const float*)d_in[1];
    const float* b_qkv = (const float*)d_in[2];
    const float* W_out = (const float*)d_in[3];
    const float* b_out = (const float*)d_in[4];
    float* out = (float*)d_out;

    __half *qkvh = nullptr, *att = nullptr, *xh = nullptr, *wqh = nullptr, *woh = nullptr;
    cudaGetSymbolAddress((void**)&qkvh, g_qkvh);
    cudaGetSymbolAddress((void**)&att,  g_att);
    cudaGetSymbolAddress((void**)&xh,   g_xh);
    cudaGetSymbolAddress((void**)&wqh,  g_wqh);
    cudaGetSymbolAddress((void**)&woh,  g_woh);

    cudaFuncSetAttribute(gemm_nt_f16<true>,  cudaFuncAttributeMaxDynamicSharedMemorySize, GEMM_SMEM);
    cudaFuncSetAttribute(gemm_nt_f16<false>, cudaFuncAttributeMaxDynamicSharedMemorySize, GEMM_SMEM);
    cudaFuncSetAttribute(attn64, cudaFuncAttributeMaxDynamicSharedMemorySize, ATTN_SMEM);

    // 0) fp32 -> fp16 conversions of GEMM inputs
    {
        int n4x = TOK * DMODEL / 4;
        f2h_kernel<<<n4x / 256, 256>>>((const float4*)x, (uint2*)xh, n4x);
        int n4q = E3 * DMODEL / 4;
        f2h_kernel<<<n4q / 256, 256>>>((const float4*)W_qkv, (uint2*)wqh, n4q);
        int n4o = DMODEL * DMODEL / 4;
        f2h_kernel<<<n4o / 256, 256>>>((const float4*)W_out, (uint2*)woh, n4o);
    }

    // 1) qkv = x @ W_qkv^T + b_qkv   [16384, 6144], fp16 out
    {
        dim3 grid(E3 / BN, TOK / BM);
        gemm_nt_f16<true><<<grid, 128, GEMM_SMEM>>>(xh, wqh, b_qkv, qkvh, TOK, E3, DMODEL);
    }

    // 2) attention per (b, h) — tensor-core QK/PV, fp32 softmax, fp16 out
    {
        attn64<<<NBATCH * NHEAD, 128, ATTN_SMEM>>>(qkvh, att);
    }

    // 3) out = att @ W_out^T + b_out  [16384, 2048], fp32 out
    {
        dim3 grid(DMODEL / BN, TOK / BM);
        gemm_nt_f16<false><<<grid, 128, GEMM_SMEM>>>(att, woh, b_out, out, TOK, DMODEL, DMODEL);
    }
}

// round 14
// speedup vs baseline: 2.2115x; 1.0025x over previous
#include <cuda_runtime.h>
#include <cuda_fp16.h>
#include <stdint.h>
#include <math.h>

// ---------------------------------------------------------------------------
// Problem constants
// ---------------------------------------------------------------------------
#define TOK      16384
#define DMODEL   2048
#define E3       6144
#define NHEAD    16
#define HD       128
#define SEQ      64
#define NBATCH   256

// Scratch (device globals: allocation rules forbid cudaMalloc)
__device__ __half g_qkvh[(size_t)TOK * E3];         // GEMM1 out, fp16
__device__ __half g_att[(size_t)TOK * DMODEL];      // attention out, fp16
__device__ __half g_xh [(size_t)TOK * DMODEL];      // x -> fp16
__device__ __half g_wqh[(size_t)E3  * DMODEL];      // W_qkv -> fp16
__device__ __half g_woh[(size_t)DMODEL * DMODEL];   // W_out -> fp16

// ---------------------------------------------------------------------------
// fp32 -> fp16 (rn) conversion
// ---------------------------------------------------------------------------
__global__ void __launch_bounds__(256)
f2h_kernel(const float4* __restrict__ in, uint2* __restrict__ out, int n4)
{
    int i = blockIdx.x * blockDim.x + threadIdx.x;
    if (i < n4) {
        float4 v = in[i];
        __half2 h0 = __floats2half2_rn(v.x, v.y);
        __half2 h1 = __floats2half2_rn(v.z, v.w);
        uint2 u;
        u.x = *(uint32_t*)&h0;
        u.y = *(uint32_t*)&h1;
        out[i] = u;
    }
}

// ---------------------------------------------------------------------------
// Common PTX helpers
// ---------------------------------------------------------------------------
__device__ __forceinline__ void cp16(uint32_t dst, const __half* src) {
    asm volatile("cp.async.cg.shared.global [%0], [%1], 16;\n" :: "r"(dst), "l"(src));
}
__device__ __forceinline__ void cp_commit() {
    asm volatile("cp.async.commit_group;\n");
}
__device__ __forceinline__ void ldsm4(uint32_t (&r)[4], uint32_t addr) {
    asm volatile("ldmatrix.sync.aligned.m8n8.x4.shared.b16 {%0,%1,%2,%3}, [%4];\n"
                 : "=r"(r[0]), "=r"(r[1]), "=r"(r[2]), "=r"(r[3]) : "r"(addr));
}
__device__ __forceinline__ void ldsm4t(uint32_t (&r)[4], uint32_t addr) {
    asm volatile("ldmatrix.sync.aligned.m8n8.x4.trans.shared.b16 {%0,%1,%2,%3}, [%4];\n"
                 : "=r"(r[0]), "=r"(r[1]), "=r"(r[2]), "=r"(r[3]) : "r"(addr));
}
__device__ __forceinline__ void mma_f16(float (&c)[4], const uint32_t (&a)[4],
                                        uint32_t b0, uint32_t b1) {
    asm volatile(
        "mma.sync.aligned.m16n8k16.row.col.f32.f16.f16.f32 "
        "{%0,%1,%2,%3},{%4,%5,%6,%7},{%8,%9},{%0,%1,%2,%3};\n"
        : "+f"(c[0]), "+f"(c[1]), "+f"(c[2]), "+f"(c[3])
        : "r"(a[0]), "r"(a[1]), "r"(a[2]), "r"(a[3]), "r"(b0), "r"(b1));
}

// ---------------------------------------------------------------------------
// FP16 tensor-core NT GEMM: C[M,N] = A[M,K] @ B[N,K]^T + bias[N]   (fp32 acc)
// CTA tile 128x128, BK=64 fp16, 3-stage cp.async, one barrier per k-iter.
// 128 threads = 4 warps (2m x 2n), warp tile 64x64. 2 CTAs/SM.
// ---------------------------------------------------------------------------
#define BM 128
#define BN 128
#define BK 64
#define STAGES 3
#define ROWB 144
#define STAGE_BYTES (BM * ROWB)                       // 18432
#define GEMM_SMEM   (STAGES * STAGE_BYTES * 2)        // 110592

template<bool HOUT>
__global__ void __launch_bounds__(128, 2)
gemm_nt_f16(const __half* __restrict__ A, const __half* __restrict__ Bm,
            const float* __restrict__ bias, void* __restrict__ Cv,
            int M, int N, int K)
{
    extern __shared__ char smc[];
    const uint32_t smA = (uint32_t)__cvta_generic_to_shared(smc);
    const uint32_t smB = smA + STAGES * STAGE_BYTES;

    const int tid  = threadIdx.x;
    const int bm   = blockIdx.y * BM;
    const int bn   = blockIdx.x * BN;
    const int warp = tid >> 5;
    const int lane = tid & 31;
    const int wm   = warp >> 1;
    const int wn   = warp & 1;

    const __half* AgP[8]; uint32_t sAP[8];
    const __half* BgP[8]; uint32_t sBP[8];
#pragma unroll
    for (int i = 0; i < 8; i++) {
        const int c   = tid + i * 128;
        const int row = c >> 3;
        const int ch  = c & 7;
        AgP[i] = A  + (size_t)(bm + row) * K + ch * 8;
        BgP[i] = Bm + (size_t)(bn + row) * K + ch * 8;
        sAP[i] = smA + (uint32_t)(row * ROWB + ch * 16);
        sBP[i] = smB + (uint32_t)(row * ROWB + ch * 16);
    }

    const int lrow = lane & 15;
    const int lkb  = (lane >> 4) * 16;
    const uint32_t aFrag = smA + (uint32_t)((wm * 64 + lrow) * ROWB + lkb);
    const uint32_t bFrag = smB + (uint32_t)((wn * 64 + lrow) * ROWB + lkb);

    float c[4][8][4];
#pragma unroll
    for (int i = 0; i < 4; i++)
#pragma unroll
        for (int j = 0; j < 8; j++)
#pragma unroll
            for (int r = 0; r < 4; r++) c[i][j][r] = 0.0f;

    const int NT = K / BK;

#pragma unroll
    for (int p = 0; p < STAGES - 1; p++) {
        const int koff = p * BK;
        const uint32_t so = (uint32_t)(p * STAGE_BYTES);
#pragma unroll
        for (int i = 0; i < 8; i++) {
            cp16(sAP[i] + so, AgP[i] + koff);
            cp16(sBP[i] + so, BgP[i] + koff);
        }
        cp_commit();
    }

    int st = 0;
    for (int s = 0; s < NT; s++) {
        if (s + 1 < NT) {
            asm volatile("cp.async.wait_group 1;\n");
        } else {
            asm volatile("cp.async.wait_group 0;\n");
        }
        __syncthreads();

        if (s + STAGES - 1 < NT) {
            const int koff = (s + STAGES - 1) * BK;
            const int slot = (s + STAGES - 1) % STAGES;
            const uint32_t so = (uint32_t)(slot * STAGE_BYTES);
#pragma unroll
            for (int i = 0; i < 8; i++) {
                cp16(sAP[i] + so, AgP[i] + koff);
                cp16(sBP[i] + so, BgP[i] + koff);
            }
            cp_commit();
        }

        {
            const uint32_t aOff = aFrag + (uint32_t)(st * STAGE_BYTES);
            const uint32_t bOff = bFrag + (uint32_t)(st * STAGE_BYTES);
#pragma unroll
            for (int kk = 0; kk < 4; kk++) {
                uint32_t a[4][4];
#pragma unroll
                for (int am = 0; am < 4; am++)
                    ldsm4(a[am], aOff + kk * 32 + am * (16 * ROWB));
                uint32_t b[4][4];
#pragma unroll
                for (int pr = 0; pr < 4; pr++)
                    ldsm4(b[pr], bOff + kk * 32 + pr * (16 * ROWB));
#pragma unroll
                for (int am = 0; am < 4; am++)
#pragma unroll
                    for (int an = 0; an < 8; an++)
                        mma_f16(c[am][an], a[am],
                                b[an >> 1][an & 1], b[an >> 1][2 + (an & 1)]);
            }
        }
        st = (st + 1 == STAGES) ? 0 : st + 1;
    }

    const int erow = lane >> 2;
    const int ecol = (lane & 3) * 2;
#pragma unroll
    for (int am = 0; am < 4; am++) {
        const int row = bm + wm * 64 + am * 16 + erow;
#pragma unroll
        for (int an = 0; an < 8; an++) {
            const int col = bn + wn * 64 + an * 8 + ecol;
            const float b0v = __ldg(bias + col);
            const float b1v = __ldg(bias + col + 1);
            if (HOUT) {
                __half* C = (__half*)Cv;
                __half2 v0 = __floats2half2_rn(c[am][an][0] + b0v, c[am][an][1] + b1v);
                __half2 v1 = __floats2half2_rn(c[am][an][2] + b0v, c[am][an][3] + b1v);
                *(__half2*)(C + (size_t)row * N + col) = v0;
                *(__half2*)(C + (size_t)(row + 8) * N + col) = v1;
            } else {
                float* C = (float*)Cv;
                float* p0 = C + (size_t)row * N + col;
                float* p1 = C + (size_t)(row + 8) * N + col;
                p0[0] = c[am][an][0] + b0v;
                p0[1] = c[am][an][1] + b1v;
                p1[0] = c[am][an][2] + b0v;
                p1[1] = c[am][an][3] + b1v;
            }
        }
    }
}

// ---------------------------------------------------------------------------
// Tensor-core attention per (batch, head). 128 threads = 4 warps.
// ---------------------------------------------------------------------------
#define QROWB 272
#define PROWB 144
#define PS_PAD 65
#define OFF_Q 0
#define OFF_K 17408
#define OFF_V 34816
#define OFF_P 52224
#define ATTN_SMEM (OFF_P + SEQ * PS_PAD * 4)   // 68864

__global__ void __launch_bounds__(128)
attn64(const __half* __restrict__ qkv, __half* __restrict__ att)
{
    extern __shared__ char smc[];
    const uint32_t sb  = (uint32_t)__cvta_generic_to_shared(smc);
    const uint32_t smQ = sb + OFF_Q;
    const uint32_t smK = sb + OFF_K;
    const uint32_t smV = sb + OFF_V;
    float* Ps = (float*)(smc + OFF_P);

    const int bh   = blockIdx.x;
    const int b    = bh >> 4;
    const int h    = bh & 15;
    const int tid  = threadIdx.x;
    const int warp = tid >> 5;
    const int lane = tid & 31;

    const __half* base = qkv + (size_t)b * SEQ * E3 + h * HD;

#pragma unroll
    for (int i = 0; i < 8; i++) {
        const int c   = tid + i * 128;
        const int row = c >> 4;
        const int ch  = c & 15;
        const __half* src = base + (size_t)row * E3 + ch * 8;
        const uint32_t d  = (uint32_t)(row * QROWB + ch * 16);
        cp16(smQ + d, src);
        cp16(smK + d, src + DMODEL);
        cp16(smV + d, src + 2 * DMODEL);
    }
    cp_commit();
    asm volatile("cp.async.wait_group 0;\n");
    __syncthreads();

    const int lrow = lane & 15;
    const int lkb  = (lane >> 4) * 16;
    const int erow = lane >> 2;
    const int ecol = (lane & 3) * 2;

    // ---- QK^T ----
    {
        const uint32_t aBase = smQ + (uint32_t)((warp * 16 + lrow) * QROWB + lkb);
        float scc[8][4];
#pragma unroll
        for (int j = 0; j < 8; j++)
#pragma unroll
            for (int r = 0; r < 4; r++) scc[j][r] = 0.0f;

#pragma unroll
        for (int kk = 0; kk < 8; kk++) {
            uint32_t a[4];
            ldsm4(a, aBase + kk * 32);
            uint32_t bb[4][4];
#pragma unroll
            for (int pr = 0; pr < 4; pr++)
                ldsm4(bb[pr], smK + (uint32_t)((pr * 16 + lrow) * QROWB + lkb) + kk * 32);
#pragma unroll
            for (int an = 0; an < 8; an++)
                mma_f16(scc[an], a, bb[an >> 1][an & 1], bb[an >> 1][2 + (an & 1)]);
        }

        const float scale = 0.022097086912079608f;  // 1/sqrt(2048)
#pragma unroll
        for (int an = 0; an < 8; an++) {
            const int q0 = warp * 16 + erow;
            const int q1 = q0 + 8;
            const int k0 = an * 8 + ecol;
            Ps[q0 * PS_PAD + k0]     = (k0     <= q0) ? scc[an][0] * scale : -1e30f;
            Ps[q0 * PS_PAD + k0 + 1] = (k0 + 1 <= q0) ? scc[an][1] * scale : -1e30f;
            Ps[q1 * PS_PAD + k0]     = (k0     <= q1) ? scc[an][2] * scale : -1e30f;
            Ps[q1 * PS_PAD + k0 + 1] = (k0 + 1 <= q1) ? scc[an][3] * scale : -1e30f;
        }
    }
    __syncthreads();

    // ---- column softmax over q (axis=-2) ----
    if (tid < SEQ) {
        const int k = tid;
        float m = -1e30f;
        for (int q = k; q < SEQ; q++) m = fmaxf(m, Ps[q * PS_PAD + k]);
        float ssum = 0.0f;
        for (int q = k; q < SEQ; q++) {
            float e = __expf(Ps[q * PS_PAD + k] - m);
            Ps[q * PS_PAD + k] = e;
            ssum += e;
        }
        const float inv = 1.0f / ssum;
        for (int q = 0; q < SEQ; q++)
            Ps[q * PS_PAD + k] = (q < k) ? 0.0f : Ps[q * PS_PAD + k] * inv;
    }
    __syncthreads();

    // ---- P -> fp16 (reuse Q region) ----
    {
        const int r  = tid >> 1;
        const int cb = (tid & 1) * 32;
#pragma unroll
        for (int j = 0; j < 32; j += 2) {
            __half2 hp = __floats2half2_rn(Ps[r * PS_PAD + cb + j],
                                           Ps[r * PS_PAD + cb + j + 1]);
            *(__half2*)(smc + OFF_Q + r * PROWB + (cb + j) * 2) = hp;
        }
    }
    __syncthreads();

    // ---- PV with ldmatrix.trans on V ----
    {
        const uint32_t aBase = smQ + (uint32_t)((warp * 16 + lrow) * PROWB + lkb);
        const int vrow_off = ((lane >> 4) & 1) * 8 + (lane & 7);
        const int vcol_off = ((lane >> 3) & 1) * 8;

        float pacc[16][4];
#pragma unroll
        for (int j = 0; j < 16; j++)
#pragma unroll
            for (int r = 0; r < 4; r++) pacc[j][r] = 0.0f;

#pragma unroll
        for (int kk = 0; kk < 4; kk++) {
            uint32_t a[4];
            ldsm4(a, aBase + kk * 32);
#pragma unroll
            for (int g = 0; g < 8; g++) {
                uint32_t vb[4];
                ldsm4t(vb, smV + (uint32_t)((kk * 16 + vrow_off) * QROWB
                                            + (g * 16 + vcol_off) * 2));
                mma_f16(pacc[2 * g],     a, vb[0], vb[2]);
                mma_f16(pacc[2 * g + 1], a, vb[1], vb[3]);
            }
        }

        __half* outp = att + (size_t)b * SEQ * DMODEL + h * HD;
        const int q0 = warp * 16 + erow;
        const int q1 = q0 + 8;
#pragma unroll
        for (int at = 0; at < 16; at++) {
            const int c0 = (at >> 1) * 16 + (at & 1) * 8 + ecol;
            __half2 v0 = __floats2half2_rn(pacc[at][0], pacc[at][1]);
            __half2 v1 = __floats2half2_rn(pacc[at][2], pacc[at][3]);
            *(__half2*)(outp + (size_t)q0 * DMODEL + c0) = v0;
            *(__half2*)(outp + (size_t)q1 * DMODEL + c0) = v1;
        }
    }
}

// ---------------------------------------------------------------------------
// Launch: 2-way M-split with stream fork so attention_lo / GEMM3_lo /
// convWo hide under GEMM1_hi. Capture-legal (event fork/join, no allocs).
// ---------------------------------------------------------------------------
#define M_HALF (TOK / 2)   // 8192

extern "C" void kernel_launch(void* const* d_in, const int* in_sizes, int n_in,
                              void* d_out, int out_size)
{
    const float* x     = (const float*)d_in[0];
    const float* W_qkv = (const float*)d_in[1];
    const float* b_qkv = (const float*)d_in[2];
    const float* W_out = (const float*)d_in[3];
    const float* b_out = (const float*)d_in[4];
    float* out = (float*)d_out;

    __half *qkvh = nullptr, *att = nullptr, *xh = nullptr, *wqh = nullptr, *woh = nullptr;
    cudaGetSymbolAddress((void**)&qkvh, g_qkvh);
    cudaGetSymbolAddress((void**)&att,  g_att);
    cudaGetSymbolAddress((void**)&xh,   g_xh);
    cudaGetSymbolAddress((void**)&wqh,  g_wqh);
    cudaGetSymbolAddress((void**)&woh,  g_woh);

    cudaFuncSetAttribute(gemm_nt_f16<true>,  cudaFuncAttributeMaxDynamicSharedMemorySize, GEMM_SMEM);
    cudaFuncSetAttribute(gemm_nt_f16<false>, cudaFuncAttributeMaxDynamicSharedMemorySize, GEMM_SMEM);
    cudaFuncSetAttribute(attn64, cudaFuncAttributeMaxDynamicSharedMemorySize, ATTN_SMEM);

    // one-time stream/event creation (host objects; no device allocations)
    static cudaStream_t s2 = nullptr;
    static cudaEvent_t e0 = nullptr, eW = nullptr, eA = nullptr, eC = nullptr;
    if (!s2) {
        cudaStreamCreateWithFlags(&s2, cudaStreamNonBlocking);
        cudaEventCreateWithFlags(&e0, cudaEventDisableTiming);
        cudaEventCreateWithFlags(&eW, cudaEventDisableTiming);
        cudaEventCreateWithFlags(&eA, cudaEventDisableTiming);
        cudaEventCreateWithFlags(&eC, cudaEventDisableTiming);
    }

    // fork s2 from origin stream
    cudaEventRecord(e0, 0);
    cudaStreamWaitEvent(s2, e0, 0);

    // s2: convert W_out (independent of everything on s0)
    {
        int n4o = DMODEL * DMODEL / 4;
        f2h_kernel<<<n4o / 256, 256, 0, s2>>>((const float4*)W_out, (uint2*)woh, n4o);
        cudaEventRecord(eW, s2);
    }

    // s0: convert x and W_qkv
    {
        int n4x = TOK * DMODEL / 4;
        f2h_kernel<<<n4x / 256, 256>>>((const float4*)x, (uint2*)xh, n4x);
        int n4q = E3 * DMODEL / 4;
        f2h_kernel<<<n4q / 256, 256>>>((const float4*)W_qkv, (uint2*)wqh, n4q);
    }

    // s0: GEMM1 lo half (token rows 0..8191)
    {
        dim3 grid(E3 / BN, M_HALF / BM);
        gemm_nt_f16<true><<<grid, 128, GEMM_SMEM>>>(xh, wqh, b_qkv, qkvh,
                                                    M_HALF, E3, DMODEL);
        cudaEventRecord(eA, 0);
    }

    // s0: GEMM1 hi half
    {
        dim3 grid(E3 / BN, M_HALF / BM);
        gemm_nt_f16<true><<<grid, 128, GEMM_SMEM>>>(
            xh + (size_t)M_HALF * DMODEL, wqh, b_qkv,
            qkvh + (size_t)M_HALF * E3, M_HALF, E3, DMODEL);
    }

    // s2: attention lo (batches 0..127) + GEMM3 lo, hidden under GEMM1 hi
    {
        cudaStreamWaitEvent(s2, eA, 0);
        attn64<<<(NBATCH / 2) * NHEAD, 128, ATTN_SMEM, s2>>>(qkvh, att);
        dim3 grid(DMODEL / BN, M_HALF / BM);
        gemm_nt_f16<false><<<grid, 128, GEMM_SMEM, s2>>>(att, woh, b_out, out,
                                                         M_HALF, DMODEL, DMODEL);
        cudaEventRecord(eC, s2);
    }

    // s0: attention hi (batches 128..255)
    {
        attn64<<<(NBATCH / 2) * NHEAD, 128, ATTN_SMEM>>>(
            qkvh + (size_t)(NBATCH / 2) * SEQ * E3,
            att + (size_t)(NBATCH / 2) * SEQ * DMODEL);
    }

    // s0: GEMM3 hi (needs convWo from s2)
    {
        cudaStreamWaitEvent(0, eW, 0);
        dim3 grid(DMODEL / BN, M_HALF / BM);
        gemm_nt_f16<false><<<grid, 128, GEMM_SMEM>>>(
            att + (size_t)M_HALF * DMODEL, woh, b_out,
            out + (size_t)M_HALF * DMODEL, M_HALF, DMODEL, DMODEL);
    }

    // join s2 back into origin stream
    cudaStreamWaitEvent(0, eC, 0);
}